// round 2
// baseline (speedup 1.0000x reference)
#include <cuda_runtime.h>

#define SEQ   128
#define BSZ   1024
#define DIN   37
#define QDIM  11
#define HID   256
#define MSLOT 20
#define ROWS  (BSZ*MSLOT)   // 20480
#define SB    (SEQ*BSZ)     // 131072

#define BM 64
#define KC 64

// ---------------- scratch (no cudaMalloc allowed) ----------------
__device__ float g_mi[(size_t)SB*HID];     // relu(memory_inputs @ C^T + Cb)   134MB
__device__ float g_tmp[(size_t)SB*HID];    // relu(mi @ V^T + Vb)              134MB
__device__ float g_sentJ[(size_t)SB*HID];  // g_tmp @ J[:,256:512]^T           134MB
__device__ float g_mem[(size_t)ROWS*HID];  // recurrent state                  21MB
__device__ float g_q[(size_t)BSZ*HID];
__device__ float g_a3[(size_t)MSLOT*HID];
__device__ float g_keyJ[(size_t)MSLOT*HID];
__device__ float g_cat[(size_t)BSZ*2*HID];

// ---------------- generic GEMM: C[r][n] = act(sum_k A[r][k]*B[n][k] + bias[n]) ----------------
// N = 256 fixed. rows guarded. act: 0=none, 1=relu.
__global__ void __launch_bounds__(256) gemm256(
    const float* __restrict__ A, int lda, int rows, int K,
    const float* __restrict__ B, int ldb,
    const float* __restrict__ bias,
    float* __restrict__ C, int act)
{
    extern __shared__ float sm[];
    float* sA    = sm;                 // BM*KC
    float* sB    = sm + BM*KC;         // KC*257
    float* sBias = sB + KC*257;        // 256

    int tid = threadIdx.x;
    int rt = tid >> 5, ct = tid & 31;
    long r0 = (long)blockIdx.x * BM;

    sBias[tid] = bias ? bias[tid] : 0.f;

    float acc[8][8];
#pragma unroll
    for (int i = 0; i < 8; i++)
#pragma unroll
        for (int j = 0; j < 8; j++) acc[i][j] = 0.f;

    for (int k0 = 0; k0 < K; k0 += KC) {
        // A chunk (row-major [BM][KC])
#pragma unroll 4
        for (int t = tid; t < BM*KC; t += 256) {
            int row = t >> 6, kk = t & 63;
            int k = k0 + kk;
            long r = r0 + row;
            sA[t] = (k < K && r < rows) ? A[r*(long)lda + k] : 0.f;
        }
        // B chunk transposed: sB[kk][n], pad 257
#pragma unroll 8
        for (int t = tid; t < 256*KC; t += 256) {
            int n = t >> 6, kk = t & 63;
            int k = k0 + kk;
            sB[kk*257 + n] = (k < K) ? B[(long)n*ldb + k] : 0.f;
        }
        __syncthreads();
#pragma unroll 8
        for (int kk = 0; kk < KC; kk++) {
            float a[8], bv[8];
#pragma unroll
            for (int i = 0; i < 8; i++) a[i] = sA[(rt*8 + i)*KC + kk];
#pragma unroll
            for (int j = 0; j < 8; j++) bv[j] = sB[kk*257 + ct + j*32];
#pragma unroll
            for (int i = 0; i < 8; i++)
#pragma unroll
                for (int j = 0; j < 8; j++) acc[i][j] = fmaf(a[i], bv[j], acc[i][j]);
        }
        __syncthreads();
    }
#pragma unroll
    for (int i = 0; i < 8; i++) {
        long row = r0 + rt*8 + i;
        if (row < rows) {
#pragma unroll
            for (int j = 0; j < 8; j++) {
                int col = ct + j*32;
                float v = acc[i][j] + sBias[col];
                if (act == 1) v = fmaxf(v, 0.f);
                C[row*256 + col] = v;
            }
        }
    }
}

// ---------------- fused per-step scan kernel ----------------
// Per 64-row tile of memories:
//   gate  = sigmoid(dot(sent_b, mem + embed_m))
//   A1    = relu(mem @ U^T + U_b)
//   G     = A1 @ J[:,0:256]^T
//   cand  = prelu(G + sentJ[s,b] + keyJ[m] + J_b)
//   mem   = normalize(mem + gate*cand)
__global__ void __launch_bounds__(256) step_kernel(
    const float* __restrict__ U_w, const float* __restrict__ U_b,
    const float* __restrict__ J_w, const float* __restrict__ J_b,
    const float* __restrict__ embed, const float* __restrict__ prelu_a,
    const float* __restrict__ mi, const float* __restrict__ sentJ,
    const float* __restrict__ keyJ, float* __restrict__ mem, int s)
{
    extern __shared__ float sm[];
    float* sMem  = sm;                    // 64*256
    float* sA1   = sMem  + 64*256;        // 64*256
    float* sB    = sA1   + 64*256;        // 64*257
    float* sSent = sB    + 64*257;        // 5*256
    float* sSJ   = sSent + 5*256;         // 5*256
    float* sUb   = sSJ   + 5*256;         // 256
    float* sJb   = sUb   + 256;           // 256
    float* sGate = sJb   + 256;           // 64

    int tid = threadIdx.x;
    int rt = tid >> 5, ct = tid & 31;
    int r0 = blockIdx.x * 64;
    int b_base = r0 / 20;
    int nb = (r0 + 63) / 20 - b_base + 1;   // <= 5

    sUb[tid] = U_b[tid];
    sJb[tid] = J_b[tid];

    for (int t = tid; t < nb*256; t += 256) {
        int bb = t >> 8, n = t & 255;
        long row = (long)s * BSZ + b_base + bb;
        sSent[t] = mi[row*256 + n];
        sSJ[t]   = sentJ[row*256 + n];
    }
    {
        const float4* gm4 = (const float4*)(mem + (long)r0 * 256);
        float4* s4 = (float4*)sMem;
#pragma unroll 4
        for (int t = tid; t < 64*64; t += 256) s4[t] = gm4[t];
    }
    __syncthreads();

    // gate: warp rt handles rows rt*8 .. rt*8+7
#pragma unroll
    for (int i = 0; i < 8; i++) {
        int lr = rt*8 + i;
        int r  = r0 + lr;
        int b  = r / 20, m = r - b*20;
        const float* emb = embed + m*256;
        const float* se  = sSent + (b - b_base)*256;
        float p = 0.f;
#pragma unroll
        for (int k = ct; k < 256; k += 32)
            p += se[k] * (sMem[lr*256 + k] + emb[k]);
#pragma unroll
        for (int o = 16; o > 0; o >>= 1) p += __shfl_xor_sync(0xffffffffu, p, o);
        if (ct == 0) sGate[lr] = 1.f / (1.f + expf(-p));
    }

    float acc[8][8];
#pragma unroll
    for (int i = 0; i < 8; i++)
#pragma unroll
        for (int j = 0; j < 8; j++) acc[i][j] = 0.f;

    // GEMM1: mem @ U^T
    for (int k0 = 0; k0 < 256; k0 += 64) {
        __syncthreads();
#pragma unroll 8
        for (int t = tid; t < 256*64; t += 256) {
            int n = t >> 6, kk = t & 63;
            sB[kk*257 + n] = U_w[n*256 + k0 + kk];
        }
        __syncthreads();
#pragma unroll 8
        for (int kk = 0; kk < 64; kk++) {
            float a[8], bv[8];
#pragma unroll
            for (int i = 0; i < 8; i++) a[i] = sMem[(rt*8 + i)*256 + k0 + kk];
#pragma unroll
            for (int j = 0; j < 8; j++) bv[j] = sB[kk*257 + ct + j*32];
#pragma unroll
            for (int i = 0; i < 8; i++)
#pragma unroll
                for (int j = 0; j < 8; j++) acc[i][j] = fmaf(a[i], bv[j], acc[i][j]);
        }
    }
    __syncthreads();

    // A1 = relu(acc + U_b)
#pragma unroll
    for (int i = 0; i < 8; i++)
#pragma unroll
        for (int j = 0; j < 8; j++) {
            int col = ct + j*32;
            sA1[(rt*8 + i)*256 + col] = fmaxf(acc[i][j] + sUb[col], 0.f);
            acc[i][j] = 0.f;
        }
    __syncthreads();

    // GEMM2: A1 @ J[:,0:256]^T
    for (int k0 = 0; k0 < 256; k0 += 64) {
        __syncthreads();
#pragma unroll 8
        for (int t = tid; t < 256*64; t += 256) {
            int n = t >> 6, kk = t & 63;
            sB[kk*257 + n] = J_w[(long)n*768 + k0 + kk];
        }
        __syncthreads();
#pragma unroll 8
        for (int kk = 0; kk < 64; kk++) {
            float a[8], bv[8];
#pragma unroll
            for (int i = 0; i < 8; i++) a[i] = sA1[(rt*8 + i)*256 + k0 + kk];
#pragma unroll
            for (int j = 0; j < 8; j++) bv[j] = sB[kk*257 + ct + j*32];
#pragma unroll
            for (int i = 0; i < 8; i++)
#pragma unroll
                for (int j = 0; j < 8; j++) acc[i][j] = fmaf(a[i], bv[j], acc[i][j]);
        }
    }

    // epilogue: cand -> update -> normalize -> write
    float alpha = prelu_a[0];
#pragma unroll
    for (int i = 0; i < 8; i++) {
        int lr = rt*8 + i;
        int r  = r0 + lr;
        int b  = r / 20, m = r - b*20;
        float g = sGate[lr];
        const float* kj = keyJ + m*256;
        const float* sj = sSJ + (b - b_base)*256;
        float upd[8];
        float ss = 0.f;
#pragma unroll
        for (int j = 0; j < 8; j++) {
            int col = ct + j*32;
            float cv = acc[i][j] + sJb[col] + sj[col] + kj[col];
            cv = cv > 0.f ? cv : alpha * cv;
            float u = sMem[lr*256 + col] + g * cv;
            upd[j] = u;
            ss += u * u;
        }
#pragma unroll
        for (int o = 16; o > 0; o >>= 1) ss += __shfl_xor_sync(0xffffffffu, ss, o);
        float inv = 1.f / (sqrtf(ss) + 1e-12f);
#pragma unroll
        for (int j = 0; j < 8; j++)
            mem[(long)r*256 + ct + j*32] = upd[j] * inv;
    }
}

// ---------------- memories init: mem[b*20+m][d] = embed[m][d] ----------------
__global__ void init_mem_kernel(const float* __restrict__ embed, float* __restrict__ mem)
{
    long idx = (long)blockIdx.x * 256 + threadIdx.x;
    int d = idx & 255;
    long rm = idx >> 8;
    int m = (int)(rm % MSLOT);
    mem[idx] = embed[m*256 + d];
}

// ---------------- attention + concat ----------------
__global__ void __launch_bounds__(256) attn_kernel(
    const float* __restrict__ mem, const float* __restrict__ q, float* __restrict__ cat)
{
    __shared__ float sQ[256];
    __shared__ float sM[MSLOT*256];
    __shared__ float sE[MSLOT];
    int b = blockIdx.x, tid = threadIdx.x;
    sQ[tid] = q[(long)b*256 + tid];
    for (int t = tid; t < MSLOT*256; t += 256) sM[t] = mem[(long)b*MSLOT*256 + t];
    __syncthreads();
    int w = tid >> 5, l = tid & 31;
    for (int m = w; m < MSLOT; m += 8) {
        float p = 0.f;
        for (int k = l; k < 256; k += 32) p += sM[m*256 + k] * sQ[k];
#pragma unroll
        for (int o = 16; o > 0; o >>= 1) p += __shfl_xor_sync(0xffffffffu, p, o);
        if (l == 0) sE[m] = p;
    }
    __syncthreads();
    float mx = -1e30f;
    for (int m = 0; m < MSLOT; m++) mx = fmaxf(mx, sE[m]);
    float sum = 0.f;
    for (int m = 0; m < MSLOT; m++) sum += expf(sE[m] - mx);
    float att = 0.f;
    for (int m = 0; m < MSLOT; m++) att += sM[m*256 + tid] * expf(sE[m] - mx);
    att /= sum;
    cat[(long)b*512 + tid]       = sQ[tid];
    cat[(long)b*512 + 256 + tid] = att;
}

// ---------------- host launcher ----------------
extern "C" void kernel_launch(void* const* d_in, const int* in_sizes, int n_in,
                              void* d_out, int out_size)
{
    const float* memory_inputs = (const float*)d_in[0];
    const float* question      = (const float*)d_in[1];
    const float* C_w = (const float*)d_in[2];
    const float* C_b = (const float*)d_in[3];
    const float* Q_w = (const float*)d_in[4];
    const float* Q_b = (const float*)d_in[5];
    const float* H_w = (const float*)d_in[6];
    const float* H_b = (const float*)d_in[7];
    const float* U_w = (const float*)d_in[8];
    const float* U_b = (const float*)d_in[9];
    const float* V_w = (const float*)d_in[10];
    const float* V_b = (const float*)d_in[11];
    const float* W_w = (const float*)d_in[12];
    const float* W_b = (const float*)d_in[13];
    const float* J_w = (const float*)d_in[14];
    const float* J_b = (const float*)d_in[15];
    const float* prelu_a = (const float*)d_in[16];
    const float* embed   = (const float*)d_in[17];
    float* out = (float*)d_out;

    size_t gemm_smem = (size_t)(BM*KC + KC*257 + 256) * sizeof(float);
    size_t step_smem = (size_t)(64*256 + 64*256 + 64*257 + 5*256 + 5*256 + 256 + 256 + 64) * sizeof(float);
    cudaFuncSetAttribute(gemm256,   cudaFuncAttributeMaxDynamicSharedMemorySize, (int)gemm_smem);
    cudaFuncSetAttribute(step_kernel, cudaFuncAttributeMaxDynamicSharedMemorySize, (int)step_smem);

    float *mi, *tmp, *sentJ, *memb, *q, *a3, *keyJ, *cat;
    cudaGetSymbolAddress((void**)&mi,    g_mi);
    cudaGetSymbolAddress((void**)&tmp,   g_tmp);
    cudaGetSymbolAddress((void**)&sentJ, g_sentJ);
    cudaGetSymbolAddress((void**)&memb,  g_mem);
    cudaGetSymbolAddress((void**)&q,     g_q);
    cudaGetSymbolAddress((void**)&a3,    g_a3);
    cudaGetSymbolAddress((void**)&keyJ,  g_keyJ);
    cudaGetSymbolAddress((void**)&cat,   g_cat);

    // init recurrent state
    init_mem_kernel<<<ROWS, 256>>>(embed, memb);

    // mi = relu(memory_inputs @ C^T + Cb)
    gemm256<<<SB/BM, 256, gemm_smem>>>(memory_inputs, DIN, SB, DIN, C_w, DIN, C_b, mi, 1);
    // q = relu(question @ Q^T + Qb)
    gemm256<<<BSZ/BM, 256, gemm_smem>>>(question, QDIM, BSZ, QDIM, Q_w, QDIM, Q_b, q, 1);
    // tmp = relu(mi @ V^T + Vb)
    gemm256<<<SB/BM, 256, gemm_smem>>>(mi, HID, SB, HID, V_w, HID, V_b, tmp, 1);
    // sentJ = tmp @ J[:,256:512]^T
    gemm256<<<SB/BM, 256, gemm_smem>>>(tmp, HID, SB, HID, J_w + 256, 768, (const float*)0, sentJ, 0);
    // a3 = relu(embed @ W^T + Wb);  keyJ = a3 @ J[:,512:768]^T
    gemm256<<<1, 256, gemm_smem>>>(embed, HID, MSLOT, HID, W_w, HID, W_b, a3, 1);
    gemm256<<<1, 256, gemm_smem>>>(a3, HID, MSLOT, HID, J_w + 512, 768, (const float*)0, keyJ, 0);

    // recurrent scan
    for (int s = 0; s < SEQ; s++)
        step_kernel<<<ROWS/64, 256, step_smem>>>(U_w, U_b, J_w, J_b, embed, prelu_a,
                                                 mi, sentJ, keyJ, memb, s);

    // attention + concat, then final projection
    attn_kernel<<<BSZ, 256>>>(memb, q, cat);
    gemm256<<<BSZ/BM, 256, gemm_smem>>>(cat, 2*HID, BSZ, 2*HID, H_w, 2*HID, H_b, out, 1);
}

// round 3
// speedup vs baseline: 1.1966x; 1.1966x over previous
#include <cuda_runtime.h>

#define SEQ   128
#define BSZ   1024
#define DIN   37
#define QDIM  11
#define HID   256
#define MSLOT 20
#define ROWS  (BSZ*MSLOT)   // 20480
#define SB    (SEQ*BSZ)     // 131072

#define BM 64
#define KC 64

// fused-scan tiling
#define TROWS 40                 // rows per tile = 2 batches
#define NTILES (ROWS/TROWS)      // 512
#define SCAN_GRID 148
#define SBSTR 258                // sB row stride (floats)

typedef unsigned long long ull;

// ---------------- scratch (no cudaMalloc allowed) ----------------
__device__ float g_mi[(size_t)SB*HID];
__device__ float g_tmp[(size_t)SB*HID];
__device__ float g_sentJ[(size_t)SB*HID];
__device__ float g_mem[(size_t)ROWS*HID];
__device__ float g_q[(size_t)BSZ*HID];
__device__ float g_a3[(size_t)MSLOT*HID];
__device__ float g_keyJ[(size_t)MSLOT*HID];
__device__ float g_cat[(size_t)BSZ*2*HID];

// ---------------- f32x2 helpers ----------------
__device__ __forceinline__ ull splat2(float a) {
    ull r; asm("mov.b64 %0, {%1, %1};" : "=l"(r) : "f"(a)); return r;
}
__device__ __forceinline__ void ffma2(ull& acc, ull a, ull b) {
    asm("fma.rn.f32x2 %0, %1, %2, %0;" : "+l"(acc) : "l"(a), "l"(b));
}
__device__ __forceinline__ float2 unpack2(ull v) {
    float2 f; asm("mov.b64 {%0, %1}, %2;" : "=f"(f.x), "=f"(f.y) : "l"(v)); return f;
}

// ---------------- generic GEMM: C[r][n] = act(sum_k A[r][k]*B[n][k] + bias[n]) ----------------
__global__ void __launch_bounds__(256) gemm256(
    const float* __restrict__ A, int lda, int rows, int K,
    const float* __restrict__ B, int ldb,
    const float* __restrict__ bias,
    float* __restrict__ C, int act)
{
    extern __shared__ float sm[];
    float* sA    = sm;                 // BM*KC
    float* sB    = sm + BM*KC;         // KC*257
    float* sBias = sB + KC*257;        // 256

    int tid = threadIdx.x;
    int rt = tid >> 5, ct = tid & 31;
    long r0 = (long)blockIdx.x * BM;

    sBias[tid] = bias ? bias[tid] : 0.f;

    float acc[8][8];
#pragma unroll
    for (int i = 0; i < 8; i++)
#pragma unroll
        for (int j = 0; j < 8; j++) acc[i][j] = 0.f;

    for (int k0 = 0; k0 < K; k0 += KC) {
#pragma unroll 4
        for (int t = tid; t < BM*KC; t += 256) {
            int row = t >> 6, kk = t & 63;
            int k = k0 + kk;
            long r = r0 + row;
            sA[t] = (k < K && r < rows) ? A[r*(long)lda + k] : 0.f;
        }
#pragma unroll 8
        for (int t = tid; t < 256*KC; t += 256) {
            int n = t >> 6, kk = t & 63;
            int k = k0 + kk;
            sB[kk*257 + n] = (k < K) ? B[(long)n*ldb + k] : 0.f;
        }
        __syncthreads();
#pragma unroll 8
        for (int kk = 0; kk < KC; kk++) {
            float a[8], bv[8];
#pragma unroll
            for (int i = 0; i < 8; i++) a[i] = sA[(rt*8 + i)*KC + kk];
#pragma unroll
            for (int j = 0; j < 8; j++) bv[j] = sB[kk*257 + ct + j*32];
#pragma unroll
            for (int i = 0; i < 8; i++)
#pragma unroll
                for (int j = 0; j < 8; j++) acc[i][j] = fmaf(a[i], bv[j], acc[i][j]);
        }
        __syncthreads();
    }
#pragma unroll
    for (int i = 0; i < 8; i++) {
        long row = r0 + rt*8 + i;
        if (row < rows) {
#pragma unroll
            for (int j = 0; j < 8; j++) {
                int col = ct + j*32;
                float v = acc[i][j] + sBias[col];
                if (act == 1) v = fmaxf(v, 0.f);
                C[row*256 + col] = v;
            }
        }
    }
}

// ---------------- fused persistent scan ----------------
// stage a KCx256 transposed weight panel: sB[kk][n] = W[n][k0+kk]
__device__ __forceinline__ void stage_panel(const float* __restrict__ W, int ldw,
                                            int k0, float* __restrict__ sB)
{
    int tid = threadIdx.x;
#pragma unroll 8
    for (int t = tid; t < 256*32; t += 256) {
        int n   = t >> 5;       // 0..255
        int kk2 = t & 31;       // 0..31, kk = 2*kk2
        float2 v = *(const float2*)(W + (long)n*ldw + k0 + 2*kk2);
        sB[(2*kk2  )*SBSTR + n] = v.x;
        sB[(2*kk2+1)*SBSTR + n] = v.y;
    }
}

__device__ __forceinline__ void compute_panel(const float* __restrict__ sBuf,
    const float* __restrict__ sA, int k0, ull acc[5][4], int rbase, int ct)
{
#pragma unroll 8
    for (int kk = 0; kk < KC; kk++) {
        const float* bp = sBuf + kk*SBSTR + 2*ct;
        ull b0 = *(const ull*)(bp);
        ull b1 = *(const ull*)(bp + 64);
        ull b2 = *(const ull*)(bp + 128);
        ull b3 = *(const ull*)(bp + 192);
#pragma unroll
        for (int i = 0; i < 5; i++) {
            ull a2 = splat2(sA[(rbase + i)*256 + k0 + kk]);
            ffma2(acc[i][0], a2, b0);
            ffma2(acc[i][1], a2, b1);
            ffma2(acc[i][2], a2, b2);
            ffma2(acc[i][3], a2, b3);
        }
    }
}

__global__ void __launch_bounds__(256) scan_kernel(
    const float* __restrict__ U_w, const float* __restrict__ U_b,
    const float* __restrict__ J_w, const float* __restrict__ J_b,
    const float* __restrict__ embed, const float* __restrict__ prelu_a,
    const float* __restrict__ mi, const float* __restrict__ sentJ,
    const float* __restrict__ keyJ, float* __restrict__ mem)
{
    extern __shared__ float sm[];
    float* sMem  = sm;                      // TROWS*256 = 10240
    float* sA1   = sMem + TROWS*256;        // 10240
    float* sB    = sA1  + TROWS*256;        // 2*KC*SBSTR = 33024
    float* sSent = sB   + 2*KC*SBSTR;       // 512
    float* sSJ   = sSent + 512;             // 512
    float* sUb   = sSJ   + 512;             // 256
    float* sJb   = sUb   + 256;             // 256
    float* sGate = sJb   + 256;             // 64

    int tid = threadIdx.x;
    int warp = tid >> 5, ct = tid & 31;
    int rbase = warp * 5;                   // 8 warps x 5 rows = 40
    float alpha = prelu_a[0];
    sUb[tid] = U_b[tid];
    sJb[tid] = J_b[tid];

    int t0 = (blockIdx.x     * NTILES) / SCAN_GRID;
    int t1 = ((blockIdx.x+1) * NTILES) / SCAN_GRID;

    for (int t = t0; t < t1; t++) {
        int r0 = t * TROWS;
        int b0 = r0 / MSLOT;                // = 2*t
        __syncthreads();                    // prev tile fully done before reloading sMem
        {
            const float4* g4 = (const float4*)(mem + (size_t)r0*256);
            float4* s4 = (float4*)sMem;
#pragma unroll 4
            for (int i = tid; i < TROWS*64; i += 256) s4[i] = g4[i];
        }

        for (int s = 0; s < SEQ; s++) {
            __syncthreads();                // sMem updates / sSJ reads from prev step done
            if (tid < 128) {
                const float4* g1 = (const float4*)(mi    + ((size_t)s*BSZ + b0)*256);
                const float4* g2 = (const float4*)(sentJ + ((size_t)s*BSZ + b0)*256);
                ((float4*)sSent)[tid] = g1[tid];
                ((float4*)sSJ)[tid]   = g2[tid];
            }
            __syncthreads();

            // ---- gate ----
#pragma unroll
            for (int i = 0; i < 5; i++) {
                int lr = rbase + i;
                int m  = lr % MSLOT;
                const float* se = sSent + ((lr >= MSLOT) ? 256 : 0);
                const float* em = embed + m*256;
                float p = 0.f;
#pragma unroll
                for (int kq = 0; kq < 8; kq++) {
                    int k = ct + kq*32;
                    p += se[k] * (sMem[lr*256 + k] + em[k]);
                }
#pragma unroll
                for (int o = 16; o > 0; o >>= 1) p += __shfl_xor_sync(0xffffffffu, p, o);
                if (ct == 0) sGate[lr] = 1.f / (1.f + expf(-p));
            }

            ull acc[5][4];
#pragma unroll
            for (int i = 0; i < 5; i++)
#pragma unroll
                for (int j = 0; j < 4; j++) acc[i][j] = 0ull;

            // ---- GEMM1: sMem @ U^T (double-buffered panels) ----
            stage_panel(U_w, 256, 0, sB);
            __syncthreads();
#pragma unroll 1
            for (int p = 0; p < 4; p++) {
                float* cur = sB + (p & 1) * KC * SBSTR;
                if (p < 3) stage_panel(U_w, 256, (p+1)*KC, sB + ((p+1)&1)*KC*SBSTR);
                compute_panel(cur, sMem, p*KC, acc, rbase, ct);
                __syncthreads();
            }

            // ---- A1 = relu(acc + U_b) ----
#pragma unroll
            for (int i = 0; i < 5; i++) {
#pragma unroll
                for (int j = 0; j < 4; j++) {
                    int col = 2*(ct + 32*j);
                    float2 v = unpack2(acc[i][j]);
                    v.x = fmaxf(v.x + sUb[col],   0.f);
                    v.y = fmaxf(v.y + sUb[col+1], 0.f);
                    *(float2*)(sA1 + (rbase+i)*256 + col) = v;
                    acc[i][j] = 0ull;
                }
            }
            __syncthreads();

            // ---- GEMM2: A1 @ J[:,0:256]^T ----
            stage_panel(J_w, 768, 0, sB);
            __syncthreads();
#pragma unroll 1
            for (int p = 0; p < 4; p++) {
                float* cur = sB + (p & 1) * KC * SBSTR;
                if (p < 3) stage_panel(J_w, 768, (p+1)*KC, sB + ((p+1)&1)*KC*SBSTR);
                compute_panel(cur, sA1, p*KC, acc, rbase, ct);
                __syncthreads();
            }

            // ---- epilogue: prelu, gated update, normalize, write sMem in place ----
#pragma unroll
            for (int i = 0; i < 5; i++) {
                int lr = rbase + i;
                int m  = lr % MSLOT;
                float g = sGate[lr];
                const float* sj = sSJ + ((lr >= MSLOT) ? 256 : 0);
                const float* kj = keyJ + m*256;
                float u[8];
                float ss = 0.f;
#pragma unroll
                for (int j = 0; j < 4; j++) {
                    int col = 2*(ct + 32*j);
                    float2 c = unpack2(acc[i][j]);
                    float c0 = c.x + sJb[col]   + sj[col]   + kj[col];
                    float c1 = c.y + sJb[col+1] + sj[col+1] + kj[col+1];
                    c0 = c0 > 0.f ? c0 : alpha * c0;
                    c1 = c1 > 0.f ? c1 : alpha * c1;
                    float u0 = sMem[lr*256 + col]     + g * c0;
                    float u1 = sMem[lr*256 + col + 1] + g * c1;
                    u[2*j] = u0; u[2*j+1] = u1;
                    ss += u0*u0 + u1*u1;
                }
#pragma unroll
                for (int o = 16; o > 0; o >>= 1) ss += __shfl_xor_sync(0xffffffffu, ss, o);
                float inv = 1.f / (sqrtf(ss) + 1e-12f);
#pragma unroll
                for (int j = 0; j < 4; j++) {
                    int col = 2*(ct + 32*j);
                    float2 w; w.x = u[2*j]*inv; w.y = u[2*j+1]*inv;
                    *(float2*)(sMem + lr*256 + col) = w;
                }
            }
        }

        __syncthreads();
        {
            const float4* s4 = (const float4*)sMem;
            float4* g4 = (float4*)(mem + (size_t)r0*256);
#pragma unroll 4
            for (int i = tid; i < TROWS*64; i += 256) g4[i] = s4[i];
        }
    }
}

// ---------------- memories init: mem[b*20+m][d] = embed[m][d] ----------------
__global__ void init_mem_kernel(const float* __restrict__ embed, float* __restrict__ mem)
{
    long idx = (long)blockIdx.x * 256 + threadIdx.x;
    int d = idx & 255;
    long rm = idx >> 8;
    int m = (int)(rm % MSLOT);
    mem[idx] = embed[m*256 + d];
}

// ---------------- attention + concat ----------------
__global__ void __launch_bounds__(256) attn_kernel(
    const float* __restrict__ mem, const float* __restrict__ q, float* __restrict__ cat)
{
    __shared__ float sQ[256];
    __shared__ float sM[MSLOT*256];
    __shared__ float sE[MSLOT];
    int b = blockIdx.x, tid = threadIdx.x;
    sQ[tid] = q[(long)b*256 + tid];
    for (int t = tid; t < MSLOT*256; t += 256) sM[t] = mem[(long)b*MSLOT*256 + t];
    __syncthreads();
    int w = tid >> 5, l = tid & 31;
    for (int m = w; m < MSLOT; m += 8) {
        float p = 0.f;
        for (int k = l; k < 256; k += 32) p += sM[m*256 + k] * sQ[k];
#pragma unroll
        for (int o = 16; o > 0; o >>= 1) p += __shfl_xor_sync(0xffffffffu, p, o);
        if (l == 0) sE[m] = p;
    }
    __syncthreads();
    float mx = -1e30f;
    for (int m = 0; m < MSLOT; m++) mx = fmaxf(mx, sE[m]);
    float sum = 0.f;
    for (int m = 0; m < MSLOT; m++) sum += expf(sE[m] - mx);
    float att = 0.f;
    for (int m = 0; m < MSLOT; m++) att += sM[m*256 + tid] * expf(sE[m] - mx);
    att /= sum;
    cat[(long)b*512 + tid]       = sQ[tid];
    cat[(long)b*512 + 256 + tid] = att;
}

// ---------------- host launcher ----------------
extern "C" void kernel_launch(void* const* d_in, const int* in_sizes, int n_in,
                              void* d_out, int out_size)
{
    const float* memory_inputs = (const float*)d_in[0];
    const float* question      = (const float*)d_in[1];
    const float* C_w = (const float*)d_in[2];
    const float* C_b = (const float*)d_in[3];
    const float* Q_w = (const float*)d_in[4];
    const float* Q_b = (const float*)d_in[5];
    const float* H_w = (const float*)d_in[6];
    const float* H_b = (const float*)d_in[7];
    const float* U_w = (const float*)d_in[8];
    const float* U_b = (const float*)d_in[9];
    const float* V_w = (const float*)d_in[10];
    const float* V_b = (const float*)d_in[11];
    const float* W_w = (const float*)d_in[12];
    const float* W_b = (const float*)d_in[13];
    const float* J_w = (const float*)d_in[14];
    const float* J_b = (const float*)d_in[15];
    const float* prelu_a = (const float*)d_in[16];
    const float* embed   = (const float*)d_in[17];
    float* out = (float*)d_out;

    size_t gemm_smem = (size_t)(BM*KC + KC*257 + 256) * sizeof(float);
    size_t scan_smem = (size_t)(TROWS*256 + TROWS*256 + 2*KC*SBSTR + 512 + 512 + 256 + 256 + 64) * sizeof(float);
    cudaFuncSetAttribute(gemm256,     cudaFuncAttributeMaxDynamicSharedMemorySize, (int)gemm_smem);
    cudaFuncSetAttribute(scan_kernel, cudaFuncAttributeMaxDynamicSharedMemorySize, (int)scan_smem);

    float *mi, *tmp, *sentJ, *memb, *q, *a3, *keyJ, *cat;
    cudaGetSymbolAddress((void**)&mi,    g_mi);
    cudaGetSymbolAddress((void**)&tmp,   g_tmp);
    cudaGetSymbolAddress((void**)&sentJ, g_sentJ);
    cudaGetSymbolAddress((void**)&memb,  g_mem);
    cudaGetSymbolAddress((void**)&q,     g_q);
    cudaGetSymbolAddress((void**)&a3,    g_a3);
    cudaGetSymbolAddress((void**)&keyJ,  g_keyJ);
    cudaGetSymbolAddress((void**)&cat,   g_cat);

    // init recurrent state
    init_mem_kernel<<<ROWS, 256>>>(embed, memb);

    // precompute (loop-invariant parts)
    gemm256<<<SB/BM, 256, gemm_smem>>>(memory_inputs, DIN, SB, DIN, C_w, DIN, C_b, mi, 1);
    gemm256<<<BSZ/BM, 256, gemm_smem>>>(question, QDIM, BSZ, QDIM, Q_w, QDIM, Q_b, q, 1);
    gemm256<<<SB/BM, 256, gemm_smem>>>(mi, HID, SB, HID, V_w, HID, V_b, tmp, 1);
    gemm256<<<SB/BM, 256, gemm_smem>>>(tmp, HID, SB, HID, J_w + 256, 768, (const float*)0, sentJ, 0);
    gemm256<<<1, 256, gemm_smem>>>(embed, HID, MSLOT, HID, W_w, HID, W_b, a3, 1);
    gemm256<<<1, 256, gemm_smem>>>(a3, HID, MSLOT, HID, J_w + 512, 768, (const float*)0, keyJ, 0);

    // fused persistent scan: one launch, state resident in SMEM
    scan_kernel<<<SCAN_GRID, 256, scan_smem>>>(U_w, U_b, J_w, J_b, embed, prelu_a,
                                               mi, sentJ, keyJ, memb);

    // attention + concat, then final projection
    attn_kernel<<<BSZ, 256>>>(memb, q, cat);
    gemm256<<<BSZ/BM, 256, gemm_smem>>>(cat, 2*HID, BSZ, 2*HID, H_w, 2*HID, H_b, out, 1);
}